// round 14
// baseline (speedup 1.0000x reference)
#include <cuda_runtime.h>
#include <cuda_bf16.h>
#include <cstdint>

#define S_ 64
#define B_ 64
#define V_ 10000
#define E_ 256
#define H_ 512

#define KSPLIT 1536           // K' = 3*H : [hi|hi|lo] x [hi|lo|hi]
#define NPAD   10112          // 79 tiles of 128

// ---------------- device scratch (static: no allocations allowed) ----------------
__device__ float g_h0[B_ * H_];
__device__ float g_y0[B_ * H_];
__device__ float g_h1all[S_ * B_ * H_];
// tree barrier: 16 leaves (128B apart) + root + generation flag; monotonic counters
__device__ unsigned g_leaf[16 * 32];
__device__ unsigned g_root;
__device__ volatile unsigned g_gen;

// bf16 split operands for the logits GEMM (A'' 12.6MB, B'' 31.1MB)
__device__ __nv_bfloat16 g_A2[(size_t)S_ * B_ * KSPLIT];
__device__ __nv_bfloat16 g_B2[(size_t)NPAD * KSPLIT];

// ---------------- XLA/Eigen fast-tanh clone (bit-exact vs reference) ----------------
// DO NOT TOUCH: trajectory is bit-exact vs XLA:CPU (error amplified ~2e4x).
__device__ __forceinline__ float tanh_xla(float x)
{
    if (fabsf(x) < 0.0004f) return x;
    float xc = fminf(fmaxf(x, -9.0f), 9.0f);
    float x2 = xc * xc;
    float a = -2.76076847742355e-16f;
    a = __fmaf_rn(a, x2, 2.00018790482477e-13f);
    a = __fmaf_rn(a, x2, -8.60467152213735e-11f);
    a = __fmaf_rn(a, x2, 5.12229709037114e-08f);
    a = __fmaf_rn(a, x2, 1.48572235717979e-05f);
    a = __fmaf_rn(a, x2, 6.37261928875436e-04f);
    a = __fmaf_rn(a, x2, 4.89352455891786e-03f);
    float num = xc * a;
    float q = 1.19825839466702e-06f;
    q = __fmaf_rn(q, x2, 1.18534705686654e-04f);
    q = __fmaf_rn(q, x2, 2.26843463243900e-03f);
    q = __fmaf_rn(q, x2, 4.89352518554385e-03f);
    return __fdiv_rn(num, q);
}

// ---------------- tree barrier: arrive (tid0) / wait (tid0), monotonic epochs ------
// 128 CTAs = 16 leaves x 8. Epoch e complete when leaf counter hits 8e (leaf-last
// forwards to root), root hits 16e (root-last publishes g_gen = e). No resets.
__device__ __forceinline__ void bar_arrive_tree(int cta, unsigned epoch)
{
    unsigned prev = atomicAdd(&g_leaf[(cta & 15) * 32], 1u);
    if (prev + 1u == epoch * 8u) {
        unsigned r = atomicAdd(&g_root, 1u);
        if (r + 1u == epoch * 16u) {
            __threadfence();
            g_gen = epoch;
        }
    }
}

__global__ void init_bar_kernel()
{
    for (int i = 0; i < 16; i++) g_leaf[i * 32] = 0u;
    g_root = 0u;
    g_gen = 0u;
}

// ---------------- cp.async helpers -------------------------------------------------
#define CPA16(dst, src) asm volatile("cp.async.cg.shared.global [%0], [%1], 16;" :: "r"(dst), "l"(src) : "memory")
#define CPC()  asm volatile("cp.async.commit_group;" ::: "memory")
#define CPW1() asm volatile("cp.async.wait_group 1;" ::: "memory")
#define CPW0() asm volatile("cp.async.wait_group 0;" ::: "memory")

__device__ __forceinline__ unsigned smem_u32(const void* p)
{
    return (unsigned)__cvta_generic_to_shared(p);
}

// ---------------- recurrence machinery (proven round 8/13) --------------------------
#define SMEM_DYN_BYTES 143616
#define XA(i) (sm + (i) * 8448)
#define XB(i) (sm + 16896 + (i) * 8448)
#define WA(i) (sm + 33792 + (i) * 512)
#define WB(i) (sm + 34816 + (i) * 512)

__device__ __forceinline__ void stage_x(float* Xs, const float* base, int ck)
{
    int row = threadIdx.x >> 5, lane = threadIdx.x & 31;
#pragma unroll
    for (int i = 0; i < 8; i++) {
        int r = row + i * 8;
        unsigned dst = smem_u32(Xs + r * 132 + lane * 4);
        CPA16(dst, base + (size_t)r * H_ + ck * 128 + lane * 4);
    }
}

__device__ __forceinline__ void stage_emb(float* Xs, const float* emb, const int* sbp, int ck)
{
    int row = threadIdx.x >> 5, lane = threadIdx.x & 31;
#pragma unroll
    for (int i = 0; i < 8; i++) {
        int r = row + i * 8;
        unsigned dst = smem_u32(Xs + r * 132 + lane * 4);
        CPA16(dst, emb + (size_t)sbp[r] + ck * 128 + lane * 4);
    }
}

__device__ __forceinline__ void stage_w(float* Ws, const float* W, int len, int colbase, int ck)
{
    if (threadIdx.x < 128) {
        int row = threadIdx.x >> 5, lane = threadIdx.x & 31;
        unsigned dst = smem_u32(Ws + row * 128 + lane * 4);
        CPA16(dst, W + (size_t)(colbase + row) * len + ck * 128 + lane * 4);
    }
}

// EXACT Eigen-order chunk: single accumulator, k strictly ascending, one fma/term
__device__ __forceinline__ float comp1(float acc, const float* Xs, const float* Ws,
                                       int b, int cj)
{
    const float4* xv = (const float4*)(Xs + b * 132);
    const float4* wv = (const float4*)(Ws + cj * 128);
#pragma unroll
    for (int k = 0; k < 32; k++) {
        float4 x = xv[k];
        float4 w = wv[k];
        acc = __fmaf_rn(x.x, w.x, acc);
        acc = __fmaf_rn(x.y, w.y, acc);
        acc = __fmaf_rn(x.z, w.z, acc);
        acc = __fmaf_rn(x.w, w.w, acc);
    }
    return acc;
}

__global__ __launch_bounds__(256, 1) void recur_kernel(
    const int* __restrict__ inputs, const float* __restrict__ hidden,
    const float* __restrict__ emb,
    const float* __restrict__ Wx0, const float* __restrict__ Wh0,
    const float* __restrict__ bh0,
    const float* __restrict__ Wy0, const float* __restrict__ by0,
    const float* __restrict__ Wx1, const float* __restrict__ Wh1,
    const float* __restrict__ bh1,
    float* __restrict__ out)
{
    extern __shared__ float sm[];
    int* sbp = (int*)(sm + 35840);
    int tid = threadIdx.x;
    int b = tid & 63;
    int cj = tid >> 6;
    int cta = blockIdx.x;
    int colbase = cta * 4;
    int col = colbase + cj;
    float* out_states = out + (size_t)S_ * B_ * V_;
    unsigned epoch = 0;

    // ---- prologue: sbp(t=0), d1 = emb[0]@Wx0 (2 chunks, pipelined)
    if (tid < 64) sbp[tid] = inputs[tid] * E_;
    __syncthreads();
    float d1 = 0.f;
    {
        stage_emb(XB(0), emb, sbp, 0);
        stage_w(WB(0), Wx0, E_, colbase, 0);
        CPC();
#pragma unroll
        for (int ck = 0; ck < 2; ck++) {
            if (ck < 1) {
                stage_emb(XB(1), emb, sbp, 1);
                stage_w(WB(1), Wx0, E_, colbase, 1);
                CPC(); CPW1();
            } else CPW0();
            __syncthreads();
            d1 = comp1(d1, XB(ck), WB(ck), b, cj);
            __syncthreads();
        }
    }
    stage_w(WA(0), Wh0, H_, colbase, 0);   // prestage phase-A chunk0 W (commits with A's CPC)

    for (int t = 0; t < S_; t++) {
        // ========== phase A: d2 = P0@Wh0 -> h0 = tanh((d1+d2)+bh0) ==========
        const float* P0 = (t == 0) ? hidden : (g_h1all + (size_t)(t - 1) * B_ * H_);
        float d2 = 0.f;
        stage_x(XA(0), P0, 0);
        CPC();
#pragma unroll
        for (int ck = 0; ck < 4; ck++) {
            int cb = ck & 1, nb = (ck + 1) & 1;
            if (ck < 3) {
                stage_x(XA(nb), P0, ck + 1);
                stage_w(WA(nb), Wh0, H_, colbase, ck + 1);
                CPC(); CPW1();
            } else CPW0();
            __syncthreads();
            d2 = comp1(d2, XA(cb), WA(cb), b, cj);
            __syncthreads();
        }
        float h0v = tanh_xla((d1 + d2) + bh0[col]);
        g_h0[(size_t)b * H_ + col] = h0v;
        if (t == S_ - 1) out_states[(size_t)b * H_ + col] = h0v;

        // ---- A->B barrier (arrive, prestage B's chunk0 W, wait)
        epoch++;
        __syncthreads();
        if (tid == 0) { __threadfence(); bar_arrive_tree(cta, epoch); }
        stage_w(WA(0), Wy0, H_, colbase, 0);
        stage_w(WB(0), Wh1, H_, colbase, 0);
        if (tid == 0) { while (g_gen < epoch) { } __threadfence(); }
        __syncthreads();

        // ========== phase B: dy = h0@Wy0, e2 = P1@Wh1 -> y0 = dy+by0 ==========
        const float* P1 = (t == 0) ? (hidden + (size_t)B_ * H_) : g_h0;
        float dy = 0.f, e2 = 0.f;
        stage_x(XA(0), g_h0, 0);
        stage_x(XB(0), P1, 0);
        CPC();
#pragma unroll
        for (int ck = 0; ck < 4; ck++) {
            int cb = ck & 1, nb = (ck + 1) & 1;
            if (ck < 3) {
                stage_x(XA(nb), g_h0, ck + 1);
                stage_x(XB(nb), P1, ck + 1);
                stage_w(WA(nb), Wy0, H_, colbase, ck + 1);
                stage_w(WB(nb), Wh1, H_, colbase, ck + 1);
                CPC(); CPW1();
            } else CPW0();
            __syncthreads();
            dy = comp1(dy, XA(cb), WA(cb), b, cj);   // independent chains: ILP=2
            e2 = comp1(e2, XB(cb), WB(cb), b, cj);
            __syncthreads();
        }
        g_y0[(size_t)b * H_ + col] = dy + by0[col];
        if (t < S_ - 1 && tid < 64) sbp[tid] = inputs[(t + 1) * B_ + tid] * E_;

        // ---- B->C barrier: arrive, then compute d1n = emb[t+1]@Wx0 (independent
        //      of y0: only needs local sbp), prestage C's chunk0 W, THEN wait.
        epoch++;
        __syncthreads();   // h-stores + sbp publish
        if (tid == 0) { __threadfence(); bar_arrive_tree(cta, epoch); }
        stage_w(WA(0), Wx1, H_, colbase, 0);
        bool doemb = (t < S_ - 1);
        float d1n = 0.f;
        if (doemb) {
            stage_emb(XB(0), emb, sbp, 0);
            stage_w(WB(0), Wx0, E_, colbase, 0);
            CPC();
#pragma unroll
            for (int ck = 0; ck < 2; ck++) {
                if (ck < 1) {
                    stage_emb(XB(1), emb, sbp, 1);
                    stage_w(WB(1), Wx0, E_, colbase, 1);
                    CPC(); CPW1();
                } else CPW0();
                __syncthreads();
                d1n = comp1(d1n, XB(ck), WB(ck), b, cj);
                __syncthreads();
            }
        }
        if (tid == 0) { while (g_gen < epoch) { } __threadfence(); }
        __syncthreads();

        // ========== phase C: e1 = y0@Wx1 -> h1 = tanh((e1+e2)+bh1) ==========
        float e1 = 0.f;
        stage_x(XA(0), g_y0, 0);
        CPC();
#pragma unroll
        for (int ck = 0; ck < 4; ck++) {
            int cb = ck & 1, nb = (ck + 1) & 1;
            if (ck < 3) {
                stage_x(XA(nb), g_y0, ck + 1);
                stage_w(WA(nb), Wx1, H_, colbase, ck + 1);
                CPC(); CPW1();
            } else CPW0();
            __syncthreads();
            e1 = comp1(e1, XA(cb), WA(cb), b, cj);
            __syncthreads();
        }
        float h1v = tanh_xla((e1 + e2) + bh1[col]);
        g_h1all[(size_t)t * B_ * H_ + (size_t)b * H_ + col] = h1v;
        if (t == S_ - 1) {
            out_states[(size_t)B_ * H_ + (size_t)b * H_ + col] = h1v;
            break;   // no trailing barrier needed after the last step
        }

        // ---- C->A barrier: arrive, prestage next A's chunk0 W, wait
        epoch++;
        __syncthreads();
        if (tid == 0) { __threadfence(); bar_arrive_tree(cta, epoch); }
        stage_w(WA(0), Wh0, H_, colbase, 0);
        if (tid == 0) { while (g_gen < epoch) { } __threadfence(); }
        __syncthreads();

        d1 = d1n;
    }
}

// ---------------- A'' pre-conversion (separate kernel: ~6.4us measured) -------------
__global__ __launch_bounds__(256) void preconvA_kernel()
{
    int row = blockIdx.x;          // 4096
    int t = threadIdx.x;           // 256 -> one float2 (2 cols) per thread
    float2 v = ((const float2*)(g_h1all + (size_t)row * H_))[t];
    __nv_bfloat16 h0 = __float2bfloat16(v.x);
    __nv_bfloat16 h1 = __float2bfloat16(v.y);
    __nv_bfloat16 l0 = __float2bfloat16(v.x - __bfloat162float(h0));
    __nv_bfloat16 l1 = __float2bfloat16(v.y - __bfloat162float(h1));
    __nv_bfloat162 hh; hh.x = h0; hh.y = h1;
    __nv_bfloat162 ll; ll.x = l0; ll.y = l1;
    __nv_bfloat162* dst = (__nv_bfloat162*)(g_A2 + (size_t)row * KSPLIT);
    dst[t] = hh; dst[256 + t] = hh; dst[512 + t] = ll;
}

// ---------------- B'' pre-conversion ------------------------------------------------
__global__ __launch_bounds__(256) void preconvB_kernel(const float* __restrict__ Wy1)
{
    int row = blockIdx.x;
    int t = threadIdx.x;
    float2 v = make_float2(0.f, 0.f);
    if (row < V_) v = ((const float2*)(Wy1 + (size_t)row * H_))[t];
    __nv_bfloat16 h0 = __float2bfloat16(v.x);
    __nv_bfloat16 h1 = __float2bfloat16(v.y);
    __nv_bfloat16 l0 = __float2bfloat16(v.x - __bfloat162float(h0));
    __nv_bfloat16 l1 = __float2bfloat16(v.y - __bfloat162float(h1));
    __nv_bfloat162 hh; hh.x = h0; hh.y = h1;
    __nv_bfloat162 ll; ll.x = l0; ll.y = l1;
    __nv_bfloat162* dst = (__nv_bfloat162*)(g_B2 + (size_t)row * KSPLIT);
    dst[t] = hh; dst[256 + t] = ll; dst[512 + t] = hh;
}

// ---------------- logits GEMM: HMMA + ldmatrix + K64 (proven round 11: 346us) -------
#define GSTR 72
#define GEMM_SMEM 73728

__device__ __forceinline__ void mma16816(float* d, const unsigned* a, const unsigned* b)
{
    asm volatile(
        "mma.sync.aligned.m16n8k16.row.col.f32.bf16.bf16.f32 "
        "{%0,%1,%2,%3}, {%4,%5,%6,%7}, {%8,%9}, {%0,%1,%2,%3};"
        : "+f"(d[0]), "+f"(d[1]), "+f"(d[2]), "+f"(d[3])
        : "r"(a[0]), "r"(a[1]), "r"(a[2]), "r"(a[3]), "r"(b[0]), "r"(b[1]));
}

__device__ __forceinline__ void ldsm4(unsigned& r0, unsigned& r1, unsigned& r2,
                                      unsigned& r3, unsigned addr)
{
    asm volatile("ldmatrix.sync.aligned.m8n8.x4.shared.b16 {%0,%1,%2,%3}, [%4];"
                 : "=r"(r0), "=r"(r1), "=r"(r2), "=r"(r3) : "r"(addr));
}

__global__ __launch_bounds__(256, 2) void gemm_bf16_kernel(
    const float* __restrict__ bias, float* __restrict__ C)
{
    extern __shared__ char smg[];
    __nv_bfloat16* Asm0 = (__nv_bfloat16*)smg;
    __nv_bfloat16* Bsm0 = (__nv_bfloat16*)(smg + 36864);
    int tid = threadIdx.x, lane = tid & 31, wid = tid >> 5;
    int wm = wid & 3, wn = wid >> 2;
    int m0 = blockIdx.y * 128, n0 = blockIdx.x * 128;
    const __nv_bfloat16* Ag = g_A2 + (size_t)m0 * KSPLIT;
    const __nv_bfloat16* Bg = g_B2 + (size_t)n0 * KSPLIT;

    float acc[2][8][4];
#pragma unroll
    for (int i = 0; i < 2; i++)
#pragma unroll
        for (int j = 0; j < 8; j++)
#pragma unroll
            for (int k = 0; k < 4; k++) acc[i][j][k] = 0.f;

    int aoff = (wm * 32 + (lane & 15)) * GSTR + (lane >> 4) * 8;
    int bsub = lane >> 3;
    int boff = (wn * 64 + (bsub >> 1) * 8 + (lane & 7)) * GSTR + (bsub & 1) * 8;

#define STG64(buf, kc)                                                              \
    {                                                                               \
        _Pragma("unroll")                                                           \
        for (int i = 0; i < 4; i++) {                                               \
            int e = tid + i * 256;                                                  \
            int row = e >> 3, seg = e & 7;                                          \
            CPA16(smem_u32(Asm0 + (buf) * 9216 + row * GSTR + seg * 8),             \
                  Ag + (size_t)row * KSPLIT + (kc) * 64 + seg * 8);                 \
            CPA16(smem_u32(Bsm0 + (buf) * 9216 + row * GSTR + seg * 8),             \
                  Bg + (size_t)row * KSPLIT + (kc) * 64 + seg * 8);                 \
        }                                                                           \
    }

    STG64(0, 0); CPC();

    const int NCH = KSPLIT / 64;
    for (int kc = 0; kc < NCH; kc++) {
        int cur = kc & 1;
        if (kc < NCH - 1) { STG64(cur ^ 1, kc + 1); CPC(); CPW1(); }
        else CPW0();
        __syncthreads();

        unsigned abase = smem_u32(Asm0 + cur * 9216);
        unsigned bbase = smem_u32(Bsm0 + cur * 9216);
#pragma unroll
        for (int s = 0; s < 4; s++) {
            int kb = s * 16;
            unsigned afr[2][4], bfr[8][2];
#pragma unroll
            for (int mf = 0; mf < 2; mf++)
                ldsm4(afr[mf][0], afr[mf][1], afr[mf][2], afr[mf][3],
                      abase + (unsigned)(aoff + mf * 16 * GSTR + kb) * 2);
#pragma unroll
            for (int p = 0; p < 4; p++) {
                unsigned t0, t1, t2, t3;
                ldsm4(t0, t1, t2, t3,
                      bbase + (unsigned)(boff + p * 16 * GSTR + kb) * 2);
                bfr[2 * p][0] = t0; bfr[2 * p][1] = t1;
                bfr[2 * p + 1][0] = t2; bfr[2 * p + 1][1] = t3;
            }
#pragma unroll
            for (int mf = 0; mf < 2; mf++)
#pragma unroll
                for (int nf = 0; nf < 8; nf++)
                    mma16816(acc[mf][nf], afr[mf], bfr[nf]);
        }
        __syncthreads();
    }

    int gr = lane >> 2, cn = (lane & 3) * 2;
#pragma unroll
    for (int mf = 0; mf < 2; mf++) {
        int r = m0 + wm * 32 + mf * 16 + gr;
#pragma unroll
        for (int nf = 0; nf < 8; nf++) {
            int c = n0 + wn * 64 + nf * 8 + cn;
            if (c < V_) {
                float2 b2 = *(const float2*)(bias + c);
                float2 o0, o1;
                o0.x = acc[mf][nf][0] + b2.x;
                o0.y = acc[mf][nf][1] + b2.y;
                o1.x = acc[mf][nf][2] + b2.x;
                o1.y = acc[mf][nf][3] + b2.y;
                *(float2*)(C + (size_t)r * V_ + c) = o0;
                *(float2*)(C + (size_t)(r + 8) * V_ + c) = o1;
            }
        }
    }
}

// ---------------- launch ----------------
extern "C" void kernel_launch(void* const* d_in, const int* in_sizes, int n_in,
                              void* d_out, int out_size)
{
    const int*   inputs = (const int*)d_in[0];
    const float* hidden = (const float*)d_in[1];
    const float* emb    = (const float*)d_in[2];
    const float* Wx0    = (const float*)d_in[3];
    const float* Wh0    = (const float*)d_in[4];
    const float* bh0    = (const float*)d_in[5];
    const float* Wy0    = (const float*)d_in[6];
    const float* by0    = (const float*)d_in[7];
    const float* Wx1    = (const float*)d_in[8];
    const float* Wh1    = (const float*)d_in[9];
    const float* bh1    = (const float*)d_in[10];
    const float* Wy1    = (const float*)d_in[11];
    const float* by1    = (const float*)d_in[12];
    float* out = (float*)d_out;

    (void)in_sizes; (void)n_in; (void)out_size;

    static int attr_done = 0;
    if (!attr_done) {
        cudaFuncSetAttribute(recur_kernel,
                             cudaFuncAttributeMaxDynamicSharedMemorySize, SMEM_DYN_BYTES);
        cudaFuncSetAttribute(gemm_bf16_kernel,
                             cudaFuncAttributeMaxDynamicSharedMemorySize, GEMM_SMEM);
        attr_done = 1;
    }

    // 1) reset tree barrier (every replay)
    init_bar_kernel<<<1, 1>>>();
    // 2) pre-split Wy1 (independent of recurrence)
    preconvB_kernel<<<NPAD, 256>>>(Wy1);
    // 3) recurrence: tree barrier + arrive/wait split with d1n overlap, bit-exact
    recur_kernel<<<128, 256, SMEM_DYN_BYTES>>>(inputs, hidden, emb,
                                               Wx0, Wh0, bh0, Wy0, by0,
                                               Wx1, Wh1, bh1, out);
    // 4) coalesced A'' split (separate kernel, ~7us)
    preconvA_kernel<<<S_ * B_, 256>>>();
    // 5) logits GEMM on tensor cores (HMMA + ldmatrix, K64 double-buffered)
    gemm_bf16_kernel<<<dim3(NPAD / 128, 32), 256, GEMM_SMEM>>>(by1, out);
}

// round 17
// speedup vs baseline: 1.2211x; 1.2211x over previous
#include <cuda_runtime.h>
#include <cuda_bf16.h>
#include <cstdint>

#define S_ 64
#define B_ 64
#define V_ 10000
#define E_ 256
#define H_ 512

#define KSPLIT 1536           // K' = 3*H : [hi|hi|lo] x [hi|lo|hi]
#define NPAD   10112          // 79 tiles of 128

// 2D partition: 4 batch-groups x 32 col-groups (minimizes X+W L2 traffic)
#define RG 4                  // batch groups
#define CG 32                 // col groups
#define BPG 16                // batches per CTA
#define CPC_ 16               // cols per CTA

// ---------------- device scratch (static: no allocations allowed) ----------------
__device__ float g_h0[B_ * H_];
__device__ float g_y0[B_ * H_];
__device__ float g_h1all[S_ * B_ * H_];
// per-batch-group barrier: 4 groups, separate cache lines, flat 32-arrival
__device__ unsigned g_cnt[RG * 32];
__device__ volatile unsigned g_genv[RG * 32];

// bf16 split operands for the logits GEMM (A'' 12.6MB, B'' 31.1MB)
__device__ __nv_bfloat16 g_A2[(size_t)S_ * B_ * KSPLIT];
__device__ __nv_bfloat16 g_B2[(size_t)NPAD * KSPLIT];

// ---------------- XLA/Eigen fast-tanh clone (bit-exact vs reference) ----------------
// DO NOT TOUCH: trajectory is bit-exact vs XLA:CPU (error amplified ~2e4x).
__device__ __forceinline__ float tanh_xla(float x)
{
    if (fabsf(x) < 0.0004f) return x;
    float xc = fminf(fmaxf(x, -9.0f), 9.0f);
    float x2 = xc * xc;
    float a = -2.76076847742355e-16f;
    a = __fmaf_rn(a, x2, 2.00018790482477e-13f);
    a = __fmaf_rn(a, x2, -8.60467152213735e-11f);
    a = __fmaf_rn(a, x2, 5.12229709037114e-08f);
    a = __fmaf_rn(a, x2, 1.48572235717979e-05f);
    a = __fmaf_rn(a, x2, 6.37261928875436e-04f);
    a = __fmaf_rn(a, x2, 4.89352455891786e-03f);
    float num = xc * a;
    float q = 1.19825839466702e-06f;
    q = __fmaf_rn(q, x2, 1.18534705686654e-04f);
    q = __fmaf_rn(q, x2, 2.26843463243900e-03f);
    q = __fmaf_rn(q, x2, 4.89352518554385e-03f);
    return __fdiv_rn(num, q);
}

// ---------------- per-group barrier (32 CTAs, own cache line) -----------------------
__device__ __forceinline__ void group_bar(int g, unsigned epoch)
{
    __syncthreads();
    if (threadIdx.x == 0) {
        __threadfence();
        unsigned prev = atomicAdd(&g_cnt[g * 32], 1u);
        if (prev == CG - 1u) {
            atomicExch(&g_cnt[g * 32], 0u);
            __threadfence();
            g_genv[g * 32] = epoch;
        } else {
            while (g_genv[g * 32] < epoch) { }
            __threadfence();
        }
    }
    __syncthreads();
}

__global__ void init_bar_kernel()
{
    for (int g = 0; g < RG; g++) {
        g_cnt[g * 32] = 0u;
        g_genv[g * 32] = 0u;
    }
}

// ---------------- cp.async helpers -------------------------------------------------
#define CPA16(dst, src) asm volatile("cp.async.cg.shared.global [%0], [%1], 16;" :: "r"(dst), "l"(src) : "memory")
#define CPC()  asm volatile("cp.async.commit_group;" ::: "memory")
#define CPW1() asm volatile("cp.async.wait_group 1;" ::: "memory")
#define CPW0() asm volatile("cp.async.wait_group 0;" ::: "memory")

__device__ __forceinline__ unsigned smem_u32(const void* p)
{
    return (unsigned)__cvta_generic_to_shared(p);
}

// ---------------- recurrence smem: tiles 16 rows x 128 k (132-padded) ---------------
// XA[2], XB[2], WA[2], WB[2] each 16*132 floats; sbp[16]
#define SD 2112
#define SMEM_DYN_BYTES 67648
#define XA(i) (sm + (i) * SD)
#define XB(i) (sm + 2 * SD + (i) * SD)
#define WA(i) (sm + 4 * SD + (i) * SD)
#define WB(i) (sm + 6 * SD + (i) * SD)

// stage X tile: 16 rows x 128 floats (2 float4/thread, warp = one row, coalesced)
__device__ __forceinline__ void stage_x16(float* Xs, const float* base, int bb, int ck)
{
#pragma unroll
    for (int i = 0; i < 2; i++) {
        int e = threadIdx.x + i * 256;
        int row = e >> 5, q = e & 31;
        CPA16(smem_u32(Xs + row * 132 + q * 4),
              base + (size_t)(bb + row) * H_ + ck * 128 + q * 4);
    }
}

__device__ __forceinline__ void stage_emb16(float* Xs, const float* emb, const int* sbp, int ck)
{
#pragma unroll
    for (int i = 0; i < 2; i++) {
        int e = threadIdx.x + i * 256;
        int row = e >> 5, q = e & 31;
        CPA16(smem_u32(Xs + row * 132 + q * 4),
              emb + (size_t)sbp[row] + ck * 128 + q * 4);
    }
}

__device__ __forceinline__ void stage_w16(float* Ws, const float* W, int len, int colbase, int ck)
{
#pragma unroll
    for (int i = 0; i < 2; i++) {
        int e = threadIdx.x + i * 256;
        int row = e >> 5, q = e & 31;
        CPA16(smem_u32(Ws + row * 132 + q * 4),
              W + (size_t)(colbase + row) * len + ck * 128 + q * 4);
    }
}

// EXACT Eigen-order chunk: single accumulator, k strictly ascending, one fma/term
__device__ __forceinline__ float comp1(float acc, const float* Xs, const float* Ws,
                                       int bl, int cl)
{
    const float4* xv = (const float4*)(Xs + bl * 132);   // broadcast in 8-lane phase
    const float4* wv = (const float4*)(Ws + cl * 132);   // 132-stride: conflict-free
#pragma unroll
    for (int k = 0; k < 32; k++) {
        float4 x = xv[k];
        float4 w = wv[k];
        acc = __fmaf_rn(x.x, w.x, acc);
        acc = __fmaf_rn(x.y, w.y, acc);
        acc = __fmaf_rn(x.z, w.z, acc);
        acc = __fmaf_rn(x.w, w.w, acc);
    }
    return acc;
}

// ---------------- recurrence: 128 CTAs = 4 batch-groups x 32 col-groups -------------
// CTA: g = bx/32 owns batches [g*16,+16); q = bx%32 owns cols [q*16,+16).
// thread = (bl 0..15) x (cl 0..15): ONE output per dot -> identical fma order as all
// previous passing rounds (bit-exact). Sync is group-local (batch deps never cross).
__global__ __launch_bounds__(256, 1) void recur_kernel(
    const int* __restrict__ inputs, const float* __restrict__ hidden,
    const float* __restrict__ emb,
    const float* __restrict__ Wx0, const float* __restrict__ Wh0,
    const float* __restrict__ bh0,
    const float* __restrict__ Wy0, const float* __restrict__ by0,
    const float* __restrict__ Wx1, const float* __restrict__ Wh1,
    const float* __restrict__ bh1,
    float* __restrict__ out)
{
    extern __shared__ float sm[];
    int* sbp = (int*)(sm + 8 * SD);
    int tid = threadIdx.x;
    int bl = tid >> 4;
    int cl = tid & 15;
    int g = blockIdx.x >> 5;
    int q = blockIdx.x & 31;
    int bb = g * BPG;
    int colbase = q * CPC_;
    int col = colbase + cl;
    int b = bb + bl;
    float* out_states = out + (size_t)S_ * B_ * V_;
    unsigned epoch = 0;

    // ---- prologue: sbp(t=0), d1 = emb[0]@Wx0 (2 chunks, pipelined)
    if (tid < BPG) sbp[tid] = inputs[bb + tid] * E_;
    __syncthreads();
    float d1 = 0.f;
    {
        stage_emb16(XB(0), emb, sbp, 0);
        stage_w16(WB(0), Wx0, E_, colbase, 0);
        CPC();
#pragma unroll
        for (int ck = 0; ck < 2; ck++) {
            if (ck < 1) {
                stage_emb16(XB(1), emb, sbp, 1);
                stage_w16(WB(1), Wx0, E_, colbase, 1);
                CPC(); CPW1();
            } else CPW0();
            __syncthreads();
            d1 = comp1(d1, XB(ck), WB(ck), bl, cl);
            __syncthreads();
        }
    }

    for (int t = 0; t < S_; t++) {
        // ========== phase A: d2 = P0@Wh0 -> h0 = tanh((d1+d2)+bh0) ==========
        const float* P0 = (t == 0) ? hidden : (g_h1all + (size_t)(t - 1) * B_ * H_);
        float d2 = 0.f;
        stage_x16(XA(0), P0, bb, 0);
        stage_w16(WA(0), Wh0, H_, colbase, 0);
        CPC();
#pragma unroll
        for (int ck = 0; ck < 4; ck++) {
            int cb = ck & 1, nb = (ck + 1) & 1;
            if (ck < 3) {
                stage_x16(XA(nb), P0, bb, ck + 1);
                stage_w16(WA(nb), Wh0, H_, colbase, ck + 1);
                CPC(); CPW1();
            } else CPW0();
            __syncthreads();
            d2 = comp1(d2, XA(cb), WA(cb), bl, cl);
            __syncthreads();
        }
        float h0v = tanh_xla((d1 + d2) + bh0[col]);
        g_h0[(size_t)b * H_ + col] = h0v;
        if (t == S_ - 1) out_states[(size_t)b * H_ + col] = h0v;
        group_bar(g, ++epoch);

        // ========== phase B: dy = h0@Wy0, e2 = P1@Wh1 -> y0 = dy+by0 ==========
        // t>0: P1 == h0 -> ONE shared X tile (halves phase-B X traffic)
        bool sepP1 = (t == 0);
        float dy = 0.f, e2 = 0.f;
        stage_x16(XA(0), g_h0, bb, 0);
        if (sepP1) stage_x16(XB(0), hidden + (size_t)B_ * H_, bb, 0);
        stage_w16(WA(0), Wy0, H_, colbase, 0);
        stage_w16(WB(0), Wh1, H_, colbase, 0);
        CPC();
#pragma unroll
        for (int ck = 0; ck < 4; ck++) {
            int cb = ck & 1, nb = (ck + 1) & 1;
            if (ck < 3) {
                stage_x16(XA(nb), g_h0, bb, ck + 1);
                if (sepP1) stage_x16(XB(nb), hidden + (size_t)B_ * H_, bb, ck + 1);
                stage_w16(WA(nb), Wy0, H_, colbase, ck + 1);
                stage_w16(WB(nb), Wh1, H_, colbase, ck + 1);
                CPC(); CPW1();
            } else CPW0();
            __syncthreads();
            dy = comp1(dy, XA(cb), WA(cb), bl, cl);                       // ILP=2
            e2 = comp1(e2, sepP1 ? XB(cb) : XA(cb), WB(cb), bl, cl);
            __syncthreads();
        }
        g_y0[(size_t)b * H_ + col] = dy + by0[col];
        if (t < S_ - 1 && tid < BPG) sbp[tid] = inputs[(t + 1) * B_ + bb + tid] * E_;
        group_bar(g, ++epoch);

        // ========== phase C: e1 = y0@Wx1 (+ prefetch d1(t+1) = emb@Wx0) ==========
        bool doemb = (t < S_ - 1);
        float e1 = 0.f, d1n = 0.f;
        stage_x16(XA(0), g_y0, bb, 0);
        stage_w16(WA(0), Wx1, H_, colbase, 0);
        if (doemb) {
            stage_emb16(XB(0), emb, sbp, 0);
            stage_w16(WB(0), Wx0, E_, colbase, 0);
        }
        CPC();
#pragma unroll
        for (int ck = 0; ck < 4; ck++) {
            int cb = ck & 1, nb = (ck + 1) & 1;
            if (ck < 3) {
                stage_x16(XA(nb), g_y0, bb, ck + 1);
                stage_w16(WA(nb), Wx1, H_, colbase, ck + 1);
                if (doemb && ck + 1 < 2) {
                    stage_emb16(XB(nb), emb, sbp, ck + 1);
                    stage_w16(WB(nb), Wx0, E_, colbase, ck + 1);
                }
                CPC(); CPW1();
            } else CPW0();
            __syncthreads();
            e1 = comp1(e1, XA(cb), WA(cb), bl, cl);
            if (doemb && ck < 2) d1n = comp1(d1n, XB(cb), WB(cb), bl, cl);
            __syncthreads();
        }
        float h1v = tanh_xla((e1 + e2) + bh1[col]);
        g_h1all[(size_t)t * B_ * H_ + (size_t)b * H_ + col] = h1v;
        if (t == S_ - 1) {
            out_states[(size_t)B_ * H_ + (size_t)b * H_ + col] = h1v;
            break;
        }
        group_bar(g, ++epoch);
        d1 = d1n;
    }
}

// ---------------- A'' pre-conversion (separate kernel: ~6.4us measured) -------------
__global__ __launch_bounds__(256) void preconvA_kernel()
{
    int row = blockIdx.x;          // 4096
    int t = threadIdx.x;           // 256 -> one float2 (2 cols) per thread
    float2 v = ((const float2*)(g_h1all + (size_t)row * H_))[t];
    __nv_bfloat16 h0 = __float2bfloat16(v.x);
    __nv_bfloat16 h1 = __float2bfloat16(v.y);
    __nv_bfloat16 l0 = __float2bfloat16(v.x - __bfloat162float(h0));
    __nv_bfloat16 l1 = __float2bfloat16(v.y - __bfloat162float(h1));
    __nv_bfloat162 hh; hh.x = h0; hh.y = h1;
    __nv_bfloat162 ll; ll.x = l0; ll.y = l1;
    __nv_bfloat162* dst = (__nv_bfloat162*)(g_A2 + (size_t)row * KSPLIT);
    dst[t] = hh; dst[256 + t] = hh; dst[512 + t] = ll;
}

// ---------------- B'' pre-conversion ------------------------------------------------
__global__ __launch_bounds__(256) void preconvB_kernel(const float* __restrict__ Wy1)
{
    int row = blockIdx.x;
    int t = threadIdx.x;
    float2 v = make_float2(0.f, 0.f);
    if (row < V_) v = ((const float2*)(Wy1 + (size_t)row * H_))[t];
    __nv_bfloat16 h0 = __float2bfloat16(v.x);
    __nv_bfloat16 h1 = __float2bfloat16(v.y);
    __nv_bfloat16 l0 = __float2bfloat16(v.x - __bfloat162float(h0));
    __nv_bfloat16 l1 = __float2bfloat16(v.y - __bfloat162float(h1));
    __nv_bfloat162 hh; hh.x = h0; hh.y = h1;
    __nv_bfloat162 ll; ll.x = l0; ll.y = l1;
    __nv_bfloat162* dst = (__nv_bfloat162*)(g_B2 + (size_t)row * KSPLIT);
    dst[t] = hh; dst[256 + t] = ll; dst[512 + t] = hh;
}

// ---------------- logits GEMM: HMMA + ldmatrix + K64 (proven round 11: 346us) -------
#define GSTR 72
#define GEMM_SMEM 73728

__device__ __forceinline__ void mma16816(float* d, const unsigned* a, const unsigned* b)
{
    asm volatile(
        "mma.sync.aligned.m16n8k16.row.col.f32.bf16.bf16.f32 "
        "{%0,%1,%2,%3}, {%4,%5,%6,%7}, {%8,%9}, {%0,%1,%2,%3};"
        : "+f"(d[0]), "+f"(d[1]), "+f"(d[2]), "+f"(d[3])
        : "r"(a[0]), "r"(a[1]), "r"(a[2]), "r"(a[3]), "r"(b[0]), "r"(b[1]));
}

__device__ __forceinline__ void ldsm4(unsigned& r0, unsigned& r1, unsigned& r2,
                                      unsigned& r3, unsigned addr)
{
    asm volatile("ldmatrix.sync.aligned.m8n8.x4.shared.b16 {%0,%1,%2,%3}, [%4];"
                 : "=r"(r0), "=r"(r1), "=r"(r2), "=r"(r3) : "r"(addr));
}

__global__ __launch_bounds__(256, 2) void gemm_bf16_kernel(
    const float* __restrict__ bias, float* __restrict__ C)
{
    extern __shared__ char smg[];
    __nv_bfloat16* Asm0 = (__nv_bfloat16*)smg;
    __nv_bfloat16* Bsm0 = (__nv_bfloat16*)(smg + 36864);
    int tid = threadIdx.x, lane = tid & 31, wid = tid >> 5;
    int wm = wid & 3, wn = wid >> 2;
    int m0 = blockIdx.y * 128, n0 = blockIdx.x * 128;
    const __nv_bfloat16* Ag = g_A2 + (size_t)m0 * KSPLIT;
    const __nv_bfloat16* Bg = g_B2 + (size_t)n0 * KSPLIT;

    float acc[2][8][4];
#pragma unroll
    for (int i = 0; i < 2; i++)
#pragma unroll
        for (int j = 0; j < 8; j++)
#pragma unroll
            for (int k = 0; k < 4; k++) acc[i][j][k] = 0.f;

    int aoff = (wm * 32 + (lane & 15)) * GSTR + (lane >> 4) * 8;
    int bsub = lane >> 3;
    int boff = (wn * 64 + (bsub >> 1) * 8 + (lane & 7)) * GSTR + (bsub & 1) * 8;

#define STG64(buf, kc)                                                              \
    {                                                                               \
        _Pragma("unroll")                                                           \
        for (int i = 0; i < 4; i++) {                                               \
            int e = tid + i * 256;                                                  \
            int row = e >> 3, seg = e & 7;                                          \
            CPA16(smem_u32(Asm0 + (buf) * 9216 + row * GSTR + seg * 8),             \
                  Ag + (size_t)row * KSPLIT + (kc) * 64 + seg * 8);                 \
            CPA16(smem_u32(Bsm0 + (buf) * 9216 + row * GSTR + seg * 8),             \
                  Bg + (size_t)row * KSPLIT + (kc) * 64 + seg * 8);                 \
        }                                                                           \
    }

    STG64(0, 0); CPC();

    const int NCH = KSPLIT / 64;
    for (int kc = 0; kc < NCH; kc++) {
        int cur = kc & 1;
        if (kc < NCH - 1) { STG64(cur ^ 1, kc + 1); CPC(); CPW1(); }
        else CPW0();
        __syncthreads();

        unsigned abase = smem_u32(Asm0 + cur * 9216);
        unsigned bbase = smem_u32(Bsm0 + cur * 9216);
#pragma unroll
        for (int s = 0; s < 4; s++) {
            int kb = s * 16;
            unsigned afr[2][4], bfr[8][2];
#pragma unroll
            for (int mf = 0; mf < 2; mf++)
                ldsm4(afr[mf][0], afr[mf][1], afr[mf][2], afr[mf][3],
                      abase + (unsigned)(aoff + mf * 16 * GSTR + kb) * 2);
#pragma unroll
            for (int p = 0; p < 4; p++) {
                unsigned t0, t1, t2, t3;
                ldsm4(t0, t1, t2, t3,
                      bbase + (unsigned)(boff + p * 16 * GSTR + kb) * 2);
                bfr[2 * p][0] = t0; bfr[2 * p][1] = t1;
                bfr[2 * p + 1][0] = t2; bfr[2 * p + 1][1] = t3;
            }
#pragma unroll
            for (int mf = 0; mf < 2; mf++)
#pragma unroll
                for (int nf = 0; nf < 8; nf++)
                    mma16816(acc[mf][nf], afr[mf], bfr[nf]);
        }
        __syncthreads();
    }

    int gr = lane >> 2, cn = (lane & 3) * 2;
#pragma unroll
    for (int mf = 0; mf < 2; mf++) {
        int r = m0 + wm * 32 + mf * 16 + gr;
#pragma unroll
        for (int nf = 0; nf < 8; nf++) {
            int c = n0 + wn * 64 + nf * 8 + cn;
            if (c < V_) {
                float2 b2 = *(const float2*)(bias + c);
                float2 o0, o1;
                o0.x = acc[mf][nf][0] + b2.x;
                o0.y = acc[mf][nf][1] + b2.y;
                o1.x = acc[mf][nf][2] + b2.x;
                o1.y = acc[mf][nf][3] + b2.y;
                *(float2*)(C + (size_t)r * V_ + c) = o0;
                *(float2*)(C + (size_t)(r + 8) * V_ + c) = o1;
            }
        }
    }
}

// ---------------- launch ----------------
extern "C" void kernel_launch(void* const* d_in, const int* in_sizes, int n_in,
                              void* d_out, int out_size)
{
    const int*   inputs = (const int*)d_in[0];
    const float* hidden = (const float*)d_in[1];
    const float* emb    = (const float*)d_in[2];
    const float* Wx0    = (const float*)d_in[3];
    const float* Wh0    = (const float*)d_in[4];
    const float* bh0    = (const float*)d_in[5];
    const float* Wy0    = (const float*)d_in[6];
    const float* by0    = (const float*)d_in[7];
    const float* Wx1    = (const float*)d_in[8];
    const float* Wh1    = (const float*)d_in[9];
    const float* bh1    = (const float*)d_in[10];
    const float* Wy1    = (const float*)d_in[11];
    const float* by1    = (const float*)d_in[12];
    float* out = (float*)d_out;

    (void)in_sizes; (void)n_in; (void)out_size;

    static int attr_done = 0;
    if (!attr_done) {
        cudaFuncSetAttribute(recur_kernel,
                             cudaFuncAttributeMaxDynamicSharedMemorySize, SMEM_DYN_BYTES);
        cudaFuncSetAttribute(gemm_bf16_kernel,
                             cudaFuncAttributeMaxDynamicSharedMemorySize, GEMM_SMEM);
        attr_done = 1;
    }

    // 1) reset per-group barriers (every replay)
    init_bar_kernel<<<1, 1>>>();
    // 2) pre-split Wy1 (independent of recurrence)
    preconvB_kernel<<<NPAD, 256>>>(Wy1);
    // 3) recurrence: 4x32 2D partition (traffic-optimal), group-local sync, bit-exact
    recur_kernel<<<128, 256, SMEM_DYN_BYTES>>>(inputs, hidden, emb,
                                               Wx0, Wh0, bh0, Wy0, by0,
                                               Wx1, Wh1, bh1, out);
    // 4) coalesced A'' split (separate kernel, ~7us)
    preconvA_kernel<<<S_ * B_, 256>>>();
    // 5) logits GEMM on tensor cores (HMMA + ldmatrix, K64 double-buffered)
    gemm_bf16_kernel<<<dim3(NPAD / 128, 32), 256, GEMM_SMEM>>>(by1, out);
}